// round 2
// baseline (speedup 1.0000x reference)
#include <cuda_runtime.h>
#include <cuda_fp16.h>

#define NN 100000
#define NE 1600000
#define FIN 128
#define HID 64
#define SCAN_NBLK 98   // ceil(NN/1024)

// ---------------- scratch (device globals; no allocation allowed) ----------------
__device__ __align__(256) __half2 g_h0h[(size_t)NN * 32];  // fp16 agg input (64 feats/node)
__device__ __align__(256) float  g_h1[(size_t)NN * HID];   // conv1 output (fp32, gemm2 input)
__device__ __align__(256) float  g_y [(size_t)NN * 16];    // per-node edge-head partials
__device__ __align__(256) float  g_dinv[NN];
__device__ __align__(256) int    g_deg[NN];
__device__ __align__(256) int    g_cursor[NN];
__device__ __align__(256) int    g_rowptr[NN + 1];
__device__ __align__(256) int    g_src[NE];
__device__ __align__(256) int    g_bsums[128];

// ---------------- f32x2 helpers ----------------
__device__ __forceinline__ unsigned long long pack2(float x, float y) {
    unsigned long long r;
    asm("mov.b64 %0, {%1,%2};" : "=l"(r) : "f"(x), "f"(y));
    return r;
}
__device__ __forceinline__ void unpack2(unsigned long long v, float& x, float& y) {
    asm("mov.b64 {%0,%1}, %2;" : "=f"(x), "=f"(y) : "l"(v));
}
__device__ __forceinline__ void fma2(unsigned long long& d, unsigned long long a,
                                     unsigned long long b) {
    asm("fma.rn.f32x2 %0, %1, %2, %0;" : "+l"(d) : "l"(a), "l"(b));
}

// ---------------- CSR build ----------------
__global__ void k_zero() {
    int i = blockIdx.x * 256 + threadIdx.x;
    if (i < NN) { g_deg[i] = 0; g_cursor[i] = 0; }
}

__global__ void k_hist(const int* __restrict__ col) {
    int e = blockIdx.x * 256 + threadIdx.x;
    if (e < NE) atomicAdd(&g_deg[col[e]], 1);
}

__global__ __launch_bounds__(1024) void k_scan1() {
    int tid = threadIdx.x;
    int i = blockIdx.x * 1024 + tid;
    int v = (i < NN) ? g_deg[i] : 0;
    if (i < NN) g_dinv[i] = rsqrtf((float)v + 1.0f);  // +1 self-loop (fused former k_dinv)
    int lane = tid & 31, wid = tid >> 5;
    int x = v;
    #pragma unroll
    for (int d = 1; d < 32; d <<= 1) {
        int y = __shfl_up_sync(0xffffffffu, x, d);
        if (lane >= d) x += y;
    }
    __shared__ int wsum[32];
    if (lane == 31) wsum[wid] = x;
    __syncthreads();
    if (wid == 0) {
        int s = wsum[lane];
        int sx = s;
        #pragma unroll
        for (int d = 1; d < 32; d <<= 1) {
            int y = __shfl_up_sync(0xffffffffu, sx, d);
            if (lane >= d) sx += y;
        }
        wsum[lane] = sx - s;  // exclusive warp offsets
    }
    __syncthreads();
    int incl = x + wsum[wid];
    if (i < NN) g_rowptr[i] = incl - v;           // exclusive scan
    if (tid == 1023) g_bsums[blockIdx.x] = incl;  // block total
}

__global__ void k_scan2() {
    int t = threadIdx.x;  // 128 threads
    int v = (t < SCAN_NBLK) ? g_bsums[t] : 0;
    int lane = t & 31, wid = t >> 5;
    int x = v;
    #pragma unroll
    for (int d = 1; d < 32; d <<= 1) {
        int y = __shfl_up_sync(0xffffffffu, x, d);
        if (lane >= d) x += y;
    }
    __shared__ int ws[4];
    if (lane == 31) ws[wid] = x;
    __syncthreads();
    int off = 0;
    for (int w = 0; w < wid; w++) off += ws[w];
    int incl = x + off;
    if (t < SCAN_NBLK) g_bsums[t] = incl - v;
    if (t == SCAN_NBLK - 1) g_rowptr[NN] = incl;  // == NE
}

__global__ __launch_bounds__(1024) void k_scan3() {
    int i = blockIdx.x * 1024 + threadIdx.x;
    if (i < NN) g_rowptr[i] += g_bsums[blockIdx.x];
}

__global__ void k_fill(const int* __restrict__ row, const int* __restrict__ col) {
    int e = blockIdx.x * 256 + threadIdx.x;
    if (e < NE) {
        int c = col[e];
        int p = g_rowptr[c] + atomicAdd(&g_cursor[c], 1);
        g_src[p] = row[e];
    }
}

// ---------------- dense GEMM: g_h0h[n,64](fp16) = A[n,K](fp32) @ W[K,64] ----------------
// f32x2 packed FMA: 32 fma2 per k instead of 64 FFMA.
template <int K, bool A_FROM_H1>
__global__ __launch_bounds__(256) void k_gemm(const float* __restrict__ Ain,
                                              const float* __restrict__ W) {
    __shared__ float Ws[K * HID];
    {
        const float4* W4 = reinterpret_cast<const float4*>(W);
        float4* S4 = reinterpret_cast<float4*>(Ws);
        for (int i = threadIdx.x; i < K * HID / 4; i += 256) S4[i] = W4[i];
    }
    __syncthreads();
    int rowi = blockIdx.x * 256 + threadIdx.x;
    if (rowi >= NN) return;
    const float* A = A_FROM_H1 ? g_h1 : Ain;

    unsigned long long acc2[32];
    #pragma unroll
    for (int p = 0; p < 32; p++) acc2[p] = 0ull;

    const float4* a4 = reinterpret_cast<const float4*>(A + (size_t)rowi * K);
    const ulonglong2* S2 = reinterpret_cast<const ulonglong2*>(Ws);
    for (int k4 = 0; k4 < K / 4; k4++) {
        float4 xq = a4[k4];
        float xs[4] = {xq.x, xq.y, xq.z, xq.w};
        #pragma unroll
        for (int u = 0; u < 4; u++) {
            unsigned long long xx = pack2(xs[u], xs[u]);
            const ulonglong2* wr = S2 + (size_t)(k4 * 4 + u) * 16;  // 16 u64x2 per k-row
            #pragma unroll
            for (int j = 0; j < 16; j++) {
                ulonglong2 w = wr[j];
                fma2(acc2[2 * j + 0], xx, w.x);
                fma2(acc2[2 * j + 1], xx, w.y);
            }
        }
    }
    // convert to fp16 and store 64B
    uint4 outv[4];
    #pragma unroll
    for (int q = 0; q < 4; q++) {
        unsigned int u[4];
        #pragma unroll
        for (int t = 0; t < 4; t++) {
            float fx, fy;
            unpack2(acc2[q * 4 + t] * 0 + acc2[q * 4 + t], fx, fy);
            __half2 h = __float22half2_rn(make_float2(fx, fy));
            u[t] = *reinterpret_cast<unsigned int*>(&h);
        }
        outv[q] = make_uint4(u[0], u[1], u[2], u[3]);
    }
    // acc2 layout: pair p holds feats (2p, 2p+1); q*4+t covers pairs 0..15 => feats 0..31
    // second half:
    uint4* dst = reinterpret_cast<uint4*>(g_h0h + (size_t)rowi * 32);
    #pragma unroll
    for (int q = 0; q < 4; q++) dst[q] = outv[q];
    #pragma unroll
    for (int q = 0; q < 4; q++) {
        unsigned int u[4];
        #pragma unroll
        for (int t = 0; t < 4; t++) {
            float fx, fy;
            unpack2(acc2[16 + q * 4 + t], fx, fy);
            __half2 h = __float22half2_rn(make_float2(fx, fy));
            u[t] = *reinterpret_cast<unsigned int*>(&h);
        }
        dst[4 + q] = make_uint4(u[0], u[1], u[2], u[3]);
    }
}

// ---------------- GCN aggregate (+optional fused edge-head GEMV) ----------------
// One warp per node; lane owns 2 features (one half2). Accumulate fp32.
// FUSE_HEAD: instead of writing h1, compute y[i] = [h@Wl_top + bl , h@Wl_bot] in-warp.
template <bool FUSE_HEAD>
__global__ __launch_bounds__(256) void k_agg(const float* __restrict__ bias,
                                             const float* __restrict__ Wl,
                                             const float* __restrict__ bl) {
    __shared__ float Wls[16 * 68];   // [o][k] transposed+merged, padded to 68
    __shared__ float hs[8][64];
    __shared__ float blc[8];
    if (FUSE_HEAD) {
        for (int i = threadIdx.x; i < 16 * 64; i += 256) {
            int o = i & 15, k = i >> 4;
            int sel = o >> 3, oo = o & 7;
            Wls[o * 68 + k] = Wl[(sel * 64 + k) * 8 + oo];
        }
        if (threadIdx.x < 8) blc[threadIdx.x] = bl[threadIdx.x];
        __syncthreads();
    }

    int gw = (blockIdx.x * 256 + threadIdx.x) >> 5;   // grid is exact: 12500 blocks
    int lane = threadIdx.x & 31;
    int w = threadIdx.x >> 5;
    float di = g_dinv[gw];
    int beg = g_rowptr[gw], end = g_rowptr[gw + 1];

    const __half2* hin = g_h0h;
    float2 hself = __half22float2(hin[(size_t)gw * 32 + lane]);
    float sw = di * di;
    float ax = sw * hself.x, ay = sw * hself.y;

    int e = beg;
    for (; e + 4 <= end; e += 4) {
        int s0 = __ldg(&g_src[e]);
        int s1 = __ldg(&g_src[e + 1]);
        int s2 = __ldg(&g_src[e + 2]);
        int s3 = __ldg(&g_src[e + 3]);
        float w0 = di * __ldg(&g_dinv[s0]);
        float w1 = di * __ldg(&g_dinv[s1]);
        float w2 = di * __ldg(&g_dinv[s2]);
        float w3 = di * __ldg(&g_dinv[s3]);
        float2 v0 = __half22float2(__ldg(&hin[(size_t)s0 * 32 + lane]));
        float2 v1 = __half22float2(__ldg(&hin[(size_t)s1 * 32 + lane]));
        float2 v2 = __half22float2(__ldg(&hin[(size_t)s2 * 32 + lane]));
        float2 v3 = __half22float2(__ldg(&hin[(size_t)s3 * 32 + lane]));
        ax += w0 * v0.x + w1 * v1.x + w2 * v2.x + w3 * v3.x;
        ay += w0 * v0.y + w1 * v1.y + w2 * v2.y + w3 * v3.y;
    }
    for (; e < end; e++) {
        int s = __ldg(&g_src[e]);
        float wv = di * __ldg(&g_dinv[s]);
        float2 v = __half22float2(__ldg(&hin[(size_t)s * 32 + lane]));
        ax += wv * v.x;
        ay += wv * v.y;
    }
    float2 b = reinterpret_cast<const float2*>(bias)[lane];
    float rx = fmaxf(ax + b.x, 0.f);
    float ry = fmaxf(ay + b.y, 0.f);

    if (!FUSE_HEAD) {
        reinterpret_cast<float2*>(g_h1)[(size_t)gw * 32 + lane] = make_float2(rx, ry);
    } else {
        hs[w][2 * lane + 0] = rx;
        hs[w][2 * lane + 1] = ry;
        __syncwarp();
        if (lane < 16) {
            float acc = (lane < 8) ? blc[lane] : 0.f;
            const float4* h4 = reinterpret_cast<const float4*>(hs[w]);
            const float4* w4 = reinterpret_cast<const float4*>(Wls + lane * 68);
            #pragma unroll
            for (int k4 = 0; k4 < 16; k4++) {
                float4 hv = h4[k4];
                float4 wv = w4[k4];
                acc += hv.x * wv.x + hv.y * wv.y + hv.z * wv.z + hv.w * wv.w;
            }
            g_y[(size_t)gw * 16 + lane] = acc;
        }
        __syncwarp();
    }
}

// ---------------- edge phase: out[e] = y[row][0:8] + y[col][8:16] ----------------
__global__ void k_edge(const int* __restrict__ row, const int* __restrict__ col,
                       float* __restrict__ out) {
    int idx = blockIdx.x * 256 + threadIdx.x;
    if (idx >= NE * 2) return;
    int e = idx >> 1, c = idx & 1;
    int r = row[e], cl = col[e];
    const float4* y4 = reinterpret_cast<const float4*>(g_y);
    float4 a = y4[(size_t)r * 4 + c];
    float4 b = y4[(size_t)cl * 4 + 2 + c];
    float4 o;
    o.x = a.x + b.x; o.y = a.y + b.y; o.z = a.z + b.z; o.w = a.w + b.w;
    reinterpret_cast<float4*>(out)[idx] = o;
}

// ---------------- launch ----------------
extern "C" void kernel_launch(void* const* d_in, const int* in_sizes, int n_in,
                              void* d_out, int out_size) {
    const float* x  = (const float*)d_in[0];
    const int*   ei = (const int*)  d_in[1];
    const float* W1 = (const float*)d_in[2];
    const float* b1 = (const float*)d_in[3];
    const float* W2 = (const float*)d_in[4];
    const float* b2 = (const float*)d_in[5];
    const float* Wl = (const float*)d_in[6];
    const float* bl = (const float*)d_in[7];
    float* out = (float*)d_out;

    const int* row = ei;        // edge_index[0]
    const int* col = ei + NE;   // edge_index[1]

    const int TB = 256;
    // CSR build
    k_zero <<<(NN + TB - 1) / TB, TB>>>();
    k_hist <<<(NE + TB - 1) / TB, TB>>>(col);
    k_scan1<<<SCAN_NBLK, 1024>>>();
    k_scan2<<<1, 128>>>();
    k_scan3<<<SCAN_NBLK, 1024>>>();
    k_fill <<<(NE + TB - 1) / TB, TB>>>(row, col);

    // conv1: h0h = fp16(x@W1) ; h1 = relu(agg(h0h)+b1)
    k_gemm<FIN, false><<<(NN + TB - 1) / TB, TB>>>(x, W1);
    k_agg<false><<<(NN * 32) / TB, TB>>>(b1, Wl, bl);

    // conv2 + fused edge head: h0h = fp16(h1@W2) ; y = head(relu(agg(h0h)+b2))
    k_gemm<HID, true><<<(NN + TB - 1) / TB, TB>>>(nullptr, W2);
    k_agg<true><<<(NN * 32) / TB, TB>>>(b2, Wl, bl);

    // per-edge sum
    k_edge<<<(NE * 2 + TB - 1) / TB, TB>>>(row, col, out);
}

// round 3
// speedup vs baseline: 1.0119x; 1.0119x over previous
#include <cuda_runtime.h>
#include <cuda_fp16.h>

#define NN 100000
#define NE 1600000
#define FIN 128
#define HID 64
#define SCAN_NBLK 98     // ceil(NN/1024)
#define CSR_B 148
#define CSR_T 1024

// ---------------- scratch (device globals; no allocation allowed) ----------------
__device__ __align__(256) __half2 g_h0h[(size_t)NN * 32];  // fp16 agg input (64 feats/node)
__device__ __align__(256) float  g_h1[(size_t)NN * HID];   // conv1 output (fp32)
__device__ __align__(256) float  g_y [(size_t)NN * 16];    // per-node edge-head partials
__device__ __align__(256) float  g_dinv[NN];
__device__ __align__(256) int    g_deg[NN];
__device__ __align__(256) int    g_cursor[NN];
__device__ __align__(256) int    g_rowptr[NN + 1];
__device__ __align__(256) int2   g_srcw[NE];               // {src, bits(dinv[src])}
__device__ __align__(256) int    g_bsums[128];
__device__ int g_barc[8];                                   // one-shot barrier counters

// ---------------- f32x2 helpers ----------------
__device__ __forceinline__ unsigned long long pack2(float x, float y) {
    unsigned long long r;
    asm("mov.b64 %0, {%1,%2};" : "=l"(r) : "f"(x), "f"(y));
    return r;
}
__device__ __forceinline__ void unpack2(unsigned long long v, float& x, float& y) {
    asm("mov.b64 {%0,%1}, %2;" : "=f"(x), "=f"(y) : "l"(v));
}
__device__ __forceinline__ void fma2(unsigned long long& d, unsigned long long a,
                                     unsigned long long b) {
    asm("fma.rn.f32x2 %0, %1, %2, %0;" : "+l"(d) : "l"(a), "l"(b));
}

// ---------------- software grid barrier (one-shot counter per barrier id) ----------------
__device__ __forceinline__ void gbar(int j) {
    __syncthreads();
    if (threadIdx.x == 0) {
        __threadfence();
        atomicAdd(&g_barc[j], 1);
        volatile int* p = &g_barc[j];
        while (*p < CSR_B) { }
        __threadfence();
    }
    __syncthreads();
}

// ---------------- fused CSR build: zero | hist | scan(+dinv) | scan2 | addback | fill ----------------
__global__ __launch_bounds__(CSR_T) void k_csr(const int* __restrict__ row,
                                               const int* __restrict__ col) {
    const int tid = threadIdx.x, bid = blockIdx.x;
    const int gt = bid * CSR_T + tid;
    const int gstride = CSR_B * CSR_T;

    // phase 0: zero degrees
    for (int i = gt; i < NN; i += gstride) g_deg[i] = 0;
    gbar(0);

    // phase 1: histogram of destination (col)
    for (int e = gt; e < NE; e += gstride) atomicAdd(&g_deg[col[e]], 1);
    gbar(1);

    // phase 2: per-chunk exclusive scan + dinv (blocks 0..97, 1024 elems each)
    int excl = 0;                       // kept in register for phase 4
    int valid = 0;
    if (bid < SCAN_NBLK) {
        int i = bid * CSR_T + tid;
        valid = (i < NN);
        int v = valid ? __ldcg(&g_deg[i]) : 0;
        if (valid) g_dinv[i] = rsqrtf((float)v + 1.0f);   // +1 self-loop
        int lane = tid & 31, wid = tid >> 5;
        int x = v;
        #pragma unroll
        for (int d = 1; d < 32; d <<= 1) {
            int y = __shfl_up_sync(0xffffffffu, x, d);
            if (lane >= d) x += y;
        }
        __shared__ int wsum[32];
        if (lane == 31) wsum[wid] = x;
        __syncthreads();
        if (wid == 0) {
            int s = wsum[lane];
            int sx = s;
            #pragma unroll
            for (int d = 1; d < 32; d <<= 1) {
                int y = __shfl_up_sync(0xffffffffu, sx, d);
                if (lane >= d) sx += y;
            }
            wsum[lane] = sx - s;
        }
        __syncthreads();
        int incl = x + wsum[wid];
        excl = incl - v;
        if (tid == 1023) g_bsums[bid] = incl;
    }
    gbar(2);

    // phase 3: block 0 scans the 98 block sums (exclusive, in place)
    {
        __shared__ int ws[4];
        int v = 0, incl = 0;
        if (bid == 0) {
            if (tid < 128) {
                v = (tid < SCAN_NBLK) ? __ldcg(&g_bsums[tid]) : 0;
                int lane = tid & 31, wid = tid >> 5;
                int x = v;
                #pragma unroll
                for (int d = 1; d < 32; d <<= 1) {
                    int y = __shfl_up_sync(0xffffffffu, x, d);
                    if (lane >= d) x += y;
                }
                if (lane == 31) ws[wid] = x;
                incl = x;
            }
            __syncthreads();
            if (tid < 128) {
                int wid = tid >> 5;
                int off = 0;
                for (int w = 0; w < wid; w++) off += ws[w];
                incl += off;
                if (tid < SCAN_NBLK) g_bsums[tid] = incl - v;
            }
        }
    }
    gbar(3);

    // phase 4: add block offsets -> final rowptr; init cursor = rowptr
    if (bid < SCAN_NBLK && valid) {
        int i = bid * CSR_T + tid;
        int rp = excl + __ldcg(&g_bsums[bid]);
        g_rowptr[i] = rp;
        g_cursor[i] = rp;
    }
    if (bid == 0 && tid == 0) g_rowptr[NN] = NE;
    gbar(4);

    // phase 5: fill CSR with packed {src, dinv[src]}
    for (int e = gt; e < NE; e += gstride) {
        int c = col[e];
        int r = row[e];
        int p = atomicAdd(&g_cursor[c], 1);
        float dv = __ldcg(&g_dinv[r]);
        g_srcw[p] = make_int2(r, __float_as_int(dv));
    }
}

// ---------------- dense GEMM: g_h0h[n,64](fp16) = A[n,K](fp32) @ W[K,64] ----------------
// 2-row register blocking (rows g and g+NN/2 for coalescing); f32x2 packed FMA.
__device__ __forceinline__ void store_row_h(const unsigned long long* acc, __half2* dst) {
    uint4* d4 = reinterpret_cast<uint4*>(dst);
    #pragma unroll
    for (int q = 0; q < 8; q++) {
        unsigned int u[4];
        #pragma unroll
        for (int t = 0; t < 4; t++) {
            float fx, fy;
            unpack2(acc[q * 4 + t], fx, fy);
            __half2 h = __float22half2_rn(make_float2(fx, fy));
            u[t] = *reinterpret_cast<unsigned int*>(&h);
        }
        d4[q] = make_uint4(u[0], u[1], u[2], u[3]);
    }
}

template <int K, bool A_FROM_H1>
__global__ __launch_bounds__(128) void k_gemm(const float* __restrict__ Ain,
                                              const float* __restrict__ W) {
    // reset CSR barrier counters for the next replay (k_csr fully done: stream order)
    if (blockIdx.x == 0 && threadIdx.x == 0) {
        #pragma unroll
        for (int j = 0; j < 8; j++) g_barc[j] = 0;
    }
    __shared__ float Ws[K * HID];
    {
        const float4* W4 = reinterpret_cast<const float4*>(W);
        float4* S4 = reinterpret_cast<float4*>(Ws);
        for (int i = threadIdx.x; i < K * HID / 4; i += 128) S4[i] = W4[i];
    }
    __syncthreads();
    int gid = blockIdx.x * 128 + threadIdx.x;
    if (gid >= NN / 2) return;
    const float* A = A_FROM_H1 ? g_h1 : Ain;
    const int r0 = gid, r1 = gid + NN / 2;

    unsigned long long accA[32], accB[32];
    #pragma unroll
    for (int p = 0; p < 32; p++) { accA[p] = 0ull; accB[p] = 0ull; }

    const float4* a40 = reinterpret_cast<const float4*>(A + (size_t)r0 * K);
    const float4* a41 = reinterpret_cast<const float4*>(A + (size_t)r1 * K);
    const ulonglong2* S2 = reinterpret_cast<const ulonglong2*>(Ws);
    for (int k4 = 0; k4 < K / 4; k4++) {
        float4 q0 = a40[k4];
        float4 q1 = a41[k4];
        float s0[4] = {q0.x, q0.y, q0.z, q0.w};
        float s1[4] = {q1.x, q1.y, q1.z, q1.w};
        #pragma unroll
        for (int u = 0; u < 4; u++) {
            unsigned long long x0 = pack2(s0[u], s0[u]);
            unsigned long long x1 = pack2(s1[u], s1[u]);
            const ulonglong2* wr = S2 + (size_t)(k4 * 4 + u) * 16;
            #pragma unroll
            for (int j = 0; j < 16; j++) {
                ulonglong2 w = wr[j];
                fma2(accA[2 * j + 0], x0, w.x);
                fma2(accA[2 * j + 1], x0, w.y);
                fma2(accB[2 * j + 0], x1, w.x);
                fma2(accB[2 * j + 1], x1, w.y);
            }
        }
    }
    store_row_h(accA, g_h0h + (size_t)r0 * 32);
    store_row_h(accB, g_h0h + (size_t)r1 * 32);
}

// ---------------- GCN aggregate (+optional fused edge-head GEMV) ----------------
// One warp per node; lane owns 2 features (one half2). Accumulate fp32.
template <bool FUSE_HEAD>
__global__ __launch_bounds__(256) void k_agg(const float* __restrict__ bias,
                                             const float* __restrict__ Wl,
                                             const float* __restrict__ bl) {
    __shared__ float Wls[16 * 68];   // [o][k] transposed+merged, padded
    __shared__ float hs[8][64];
    __shared__ float blc[8];
    if (FUSE_HEAD) {
        for (int i = threadIdx.x; i < 16 * 64; i += 256) {
            int o = i & 15, k = i >> 4;
            int sel = o >> 3, oo = o & 7;
            Wls[o * 68 + k] = Wl[(sel * 64 + k) * 8 + oo];
        }
        if (threadIdx.x < 8) blc[threadIdx.x] = bl[threadIdx.x];
        __syncthreads();
    }

    int gw = (blockIdx.x * 256 + threadIdx.x) >> 5;   // grid exact: 12500 blocks
    int lane = threadIdx.x & 31;
    int w = threadIdx.x >> 5;
    float di = g_dinv[gw];
    int beg = g_rowptr[gw], end = g_rowptr[gw + 1];

    const __half2* hin = g_h0h;
    float2 hself = __half22float2(hin[(size_t)gw * 32 + lane]);
    float sw = di * di;
    float ax = sw * hself.x, ay = sw * hself.y;

    int e = beg;
    for (; e + 4 <= end; e += 4) {
        int2 p0 = __ldg(&g_srcw[e]);
        int2 p1 = __ldg(&g_srcw[e + 1]);
        int2 p2 = __ldg(&g_srcw[e + 2]);
        int2 p3 = __ldg(&g_srcw[e + 3]);
        float w0 = di * __int_as_float(p0.y);
        float w1 = di * __int_as_float(p1.y);
        float w2 = di * __int_as_float(p2.y);
        float w3 = di * __int_as_float(p3.y);
        float2 v0 = __half22float2(__ldg(&hin[(size_t)p0.x * 32 + lane]));
        float2 v1 = __half22float2(__ldg(&hin[(size_t)p1.x * 32 + lane]));
        float2 v2 = __half22float2(__ldg(&hin[(size_t)p2.x * 32 + lane]));
        float2 v3 = __half22float2(__ldg(&hin[(size_t)p3.x * 32 + lane]));
        ax += w0 * v0.x + w1 * v1.x + w2 * v2.x + w3 * v3.x;
        ay += w0 * v0.y + w1 * v1.y + w2 * v2.y + w3 * v3.y;
    }
    for (; e < end; e++) {
        int2 pp = __ldg(&g_srcw[e]);
        float wv = di * __int_as_float(pp.y);
        float2 v = __half22float2(__ldg(&hin[(size_t)pp.x * 32 + lane]));
        ax += wv * v.x;
        ay += wv * v.y;
    }
    float2 b = reinterpret_cast<const float2*>(bias)[lane];
    float rx = fmaxf(ax + b.x, 0.f);
    float ry = fmaxf(ay + b.y, 0.f);

    if (!FUSE_HEAD) {
        reinterpret_cast<float2*>(g_h1)[(size_t)gw * 32 + lane] = make_float2(rx, ry);
    } else {
        hs[w][2 * lane + 0] = rx;
        hs[w][2 * lane + 1] = ry;
        __syncwarp();
        if (lane < 16) {
            float acc = (lane < 8) ? blc[lane] : 0.f;
            const float4* h4 = reinterpret_cast<const float4*>(hs[w]);
            const float4* w4 = reinterpret_cast<const float4*>(Wls + lane * 68);
            #pragma unroll
            for (int k4 = 0; k4 < 16; k4++) {
                float4 hv = h4[k4];
                float4 wv = w4[k4];
                acc += hv.x * wv.x + hv.y * wv.y + hv.z * wv.z + hv.w * wv.w;
            }
            g_y[(size_t)gw * 16 + lane] = acc;
        }
        __syncwarp();
    }
}

// ---------------- edge phase: out[e] = y[row][0:8] + y[col][8:16] ----------------
__global__ void k_edge(const int* __restrict__ row, const int* __restrict__ col,
                       float* __restrict__ out) {
    int idx = blockIdx.x * 256 + threadIdx.x;
    if (idx >= NE * 2) return;
    int e = idx >> 1, c = idx & 1;
    int r = row[e], cl = col[e];
    const float4* y4 = reinterpret_cast<const float4*>(g_y);
    float4 a = y4[(size_t)r * 4 + c];
    float4 b = y4[(size_t)cl * 4 + 2 + c];
    float4 o;
    o.x = a.x + b.x; o.y = a.y + b.y; o.z = a.z + b.z; o.w = a.w + b.w;
    reinterpret_cast<float4*>(out)[idx] = o;
}

// ---------------- launch ----------------
extern "C" void kernel_launch(void* const* d_in, const int* in_sizes, int n_in,
                              void* d_out, int out_size) {
    const float* x  = (const float*)d_in[0];
    const int*   ei = (const int*)  d_in[1];
    const float* W1 = (const float*)d_in[2];
    const float* b1 = (const float*)d_in[3];
    const float* W2 = (const float*)d_in[4];
    const float* b2 = (const float*)d_in[5];
    const float* Wl = (const float*)d_in[6];
    const float* bl = (const float*)d_in[7];
    float* out = (float*)d_out;

    const int* row = ei;        // edge_index[0]
    const int* col = ei + NE;   // edge_index[1]

    // fused CSR build (1 kernel, software grid barriers)
    k_csr<<<CSR_B, CSR_T>>>(row, col);

    // conv1: h0h = fp16(x@W1) ; h1 = relu(agg(h0h)+b1)
    k_gemm<FIN, false><<<(NN / 2 + 127) / 128, 128>>>(x, W1);
    k_agg<false><<<(NN * 32) / 256, 256>>>(b1, Wl, bl);

    // conv2 + fused edge head
    k_gemm<HID, true><<<(NN / 2 + 127) / 128, 128>>>(nullptr, W2);
    k_agg<true><<<(NN * 32) / 256, 256>>>(b2, Wl, bl);

    // per-edge sum
    k_edge<<<(NE * 2 + 255) / 256, 256>>>(row, col, out);
}

// round 5
// speedup vs baseline: 1.2483x; 1.2336x over previous
#include <cuda_runtime.h>
#include <cuda_fp16.h>

#define NN 100000
#define NE 1600000
#define FIN 128
#define HID 64
#define SCAN_NBLK 98     // ceil(NN/1024)
#define CSR_B 148
#define CSR_T 1024

typedef unsigned int uint32;

// ---------------- scratch (device globals; no allocation allowed) ----------------
__device__ __align__(256) __half2 g_h0h[(size_t)NN * 32];  // fp16 agg input (64 feats/node)
__device__ __align__(256) __half2 g_h1h[(size_t)NN * 32];  // conv1 output (fp16)
__device__ __align__(256) float  g_y [(size_t)NN * 16];    // per-node edge-head partials
__device__ __align__(256) float  g_dinv[NN];
__device__ __align__(256) int    g_deg[NN];
__device__ __align__(256) int    g_cursor[NN];
__device__ __align__(256) int    g_rowptr[NN + 1];
__device__ __align__(256) int2   g_srcw[NE];               // {src, bits(dinv[src])}
__device__ __align__(256) int    g_bsums[128];
__device__ int g_barc[8];                                   // one-shot barrier counters

// ---------------- software grid barrier ----------------
__device__ __forceinline__ void gbar(int j) {
    __syncthreads();
    if (threadIdx.x == 0) {
        __threadfence();
        atomicAdd(&g_barc[j], 1);
        volatile int* p = &g_barc[j];
        while (*p < CSR_B) { }
        __threadfence();
    }
    __syncthreads();
}

// ---------------- fused CSR build ----------------
__global__ __launch_bounds__(CSR_T) void k_csr(const int* __restrict__ row,
                                               const int* __restrict__ col) {
    const int tid = threadIdx.x, bid = blockIdx.x;
    const int gt = bid * CSR_T + tid;
    const int gstride = CSR_B * CSR_T;

    for (int i = gt; i < NN; i += gstride) g_deg[i] = 0;
    gbar(0);

    for (int e = gt; e < NE; e += gstride) atomicAdd(&g_deg[col[e]], 1);
    gbar(1);

    int excl = 0;
    int valid = 0;
    if (bid < SCAN_NBLK) {
        int i = bid * CSR_T + tid;
        valid = (i < NN);
        int v = valid ? __ldcg(&g_deg[i]) : 0;
        if (valid) g_dinv[i] = rsqrtf((float)v + 1.0f);   // +1 self-loop
        int lane = tid & 31, wid = tid >> 5;
        int x = v;
        #pragma unroll
        for (int d = 1; d < 32; d <<= 1) {
            int y = __shfl_up_sync(0xffffffffu, x, d);
            if (lane >= d) x += y;
        }
        __shared__ int wsum[32];
        if (lane == 31) wsum[wid] = x;
        __syncthreads();
        if (wid == 0) {
            int s = wsum[lane];
            int sx = s;
            #pragma unroll
            for (int d = 1; d < 32; d <<= 1) {
                int y = __shfl_up_sync(0xffffffffu, sx, d);
                if (lane >= d) sx += y;
            }
            wsum[lane] = sx - s;
        }
        __syncthreads();
        int incl = x + wsum[wid];
        excl = incl - v;
        if (tid == 1023) g_bsums[bid] = incl;
    }
    gbar(2);

    {
        __shared__ int ws[4];
        int v = 0, incl = 0;
        if (bid == 0) {
            if (tid < 128) {
                v = (tid < SCAN_NBLK) ? __ldcg(&g_bsums[tid]) : 0;
                int lane = tid & 31, wid = tid >> 5;
                int x = v;
                #pragma unroll
                for (int d = 1; d < 32; d <<= 1) {
                    int y = __shfl_up_sync(0xffffffffu, x, d);
                    if (lane >= d) x += y;
                }
                if (lane == 31) ws[wid] = x;
                incl = x;
            }
            __syncthreads();
            if (tid < 128) {
                int wid = tid >> 5;
                int off = 0;
                for (int w = 0; w < wid; w++) off += ws[w];
                incl += off;
                if (tid < SCAN_NBLK) g_bsums[tid] = incl - v;
            }
        }
    }
    gbar(3);

    if (bid < SCAN_NBLK && valid) {
        int i = bid * CSR_T + tid;
        int rp = excl + __ldcg(&g_bsums[bid]);
        g_rowptr[i] = rp;
        g_cursor[i] = rp;
    }
    if (bid == 0 && tid == 0) g_rowptr[NN] = NE;
    gbar(4);

    for (int e = gt; e < NE; e += gstride) {
        int c = col[e];
        int r = row[e];
        int p = atomicAdd(&g_cursor[c], 1);
        float dv = __ldcg(&g_dinv[r]);
        g_srcw[p] = make_int2(r, __float_as_int(dv));
    }
}

// ---------------- tensor-core GEMM: g_h0h[n,64](fp16) = A[n,K] @ W[K,64] ----------------
// mma.sync.m16n8k16 (fp16 in, fp32 accum). Block = 4 warps x 16 rows = 64 rows.
__device__ __forceinline__ void mma16816(float d[4], uint32 a0, uint32 a1, uint32 a2,
                                         uint32 a3, uint32 b0, uint32 b1) {
    asm volatile(
        "mma.sync.aligned.m16n8k16.row.col.f32.f16.f16.f32 "
        "{%0,%1,%2,%3}, {%4,%5,%6,%7}, {%8,%9}, {%0,%1,%2,%3};"
        : "+f"(d[0]), "+f"(d[1]), "+f"(d[2]), "+f"(d[3])
        : "r"(a0), "r"(a1), "r"(a2), "r"(a3), "r"(b0), "r"(b1));
}

// A_HALF=false: A = Af (fp32, gmem input).  A_HALF=true: A = g_h1h (device global,
// selected INSIDE device code — host code must never touch device symbols).
template <int K, bool A_HALF>
__global__ __launch_bounds__(128) void k_gemm_mma(const float* __restrict__ Af,
                                                  const float* __restrict__ W) {
    // reset CSR barrier counters for the next graph replay (k_csr done: stream order)
    if (blockIdx.x == 0 && threadIdx.x == 0) {
        #pragma unroll
        for (int j = 0; j < 8; j++) g_barc[j] = 0;
    }
    __shared__ __half Wt[64][K + 8];    // W transposed [n][k], padded: conflict-free b-frag
    __shared__ __half outs[4][16][66];  // per-warp epilogue staging

    for (int i = threadIdx.x; i < K * 64; i += 128) {
        int k = i >> 6, n = i & 63;
        Wt[n][k] = __float2half(W[i]);
    }
    __syncthreads();

    const __half* Ah = reinterpret_cast<const __half*>(g_h1h);  // device-side symbol use

    const int warp = threadIdx.x >> 5, lane = threadIdx.x & 31;
    const int gr = lane >> 2;           // 0..7
    const int kc = (lane & 3) * 2;      // 0,2,4,6
    const int r0 = blockIdx.x * 64 + warp * 16 + gr;
    const int r1 = r0 + 8;
    const bool v0 = r0 < NN, v1 = r1 < NN;

    float d[8][4];
    #pragma unroll
    for (int nt = 0; nt < 8; nt++)
        #pragma unroll
        for (int t = 0; t < 4; t++) d[nt][t] = 0.f;

    #pragma unroll
    for (int q = 0; q < K / 16; q++) {
        int k0 = q * 16 + kc;
        uint32 a0 = 0, a1 = 0, a2 = 0, a3 = 0;
        if (A_HALF) {
            if (v0) {
                a0 = *reinterpret_cast<const uint32*>(Ah + (size_t)r0 * K + k0);
                a2 = *reinterpret_cast<const uint32*>(Ah + (size_t)r0 * K + k0 + 8);
            }
            if (v1) {
                a1 = *reinterpret_cast<const uint32*>(Ah + (size_t)r1 * K + k0);
                a3 = *reinterpret_cast<const uint32*>(Ah + (size_t)r1 * K + k0 + 8);
            }
        } else {
            if (v0) {
                float2 f0 = *reinterpret_cast<const float2*>(Af + (size_t)r0 * K + k0);
                float2 f2 = *reinterpret_cast<const float2*>(Af + (size_t)r0 * K + k0 + 8);
                __half2 h0 = __float22half2_rn(f0), h2 = __float22half2_rn(f2);
                a0 = *reinterpret_cast<uint32*>(&h0);
                a2 = *reinterpret_cast<uint32*>(&h2);
            }
            if (v1) {
                float2 f1 = *reinterpret_cast<const float2*>(Af + (size_t)r1 * K + k0);
                float2 f3 = *reinterpret_cast<const float2*>(Af + (size_t)r1 * K + k0 + 8);
                __half2 h1 = __float22half2_rn(f1), h3 = __float22half2_rn(f3);
                a1 = *reinterpret_cast<uint32*>(&h1);
                a3 = *reinterpret_cast<uint32*>(&h3);
            }
        }
        #pragma unroll
        for (int nt = 0; nt < 8; nt++) {
            int n = nt * 8 + gr;
            uint32 b0 = *reinterpret_cast<const uint32*>(&Wt[n][k0]);
            uint32 b1 = *reinterpret_cast<const uint32*>(&Wt[n][k0 + 8]);
            mma16816(d[nt], a0, a1, a2, a3, b0, b1);
        }
    }

    // epilogue: fragment -> smem (fp16) -> coalesced row stores
    #pragma unroll
    for (int nt = 0; nt < 8; nt++) {
        int c = nt * 8 + kc;
        *reinterpret_cast<__half2*>(&outs[warp][gr][c])     = __floats2half2_rn(d[nt][0], d[nt][1]);
        *reinterpret_cast<__half2*>(&outs[warp][gr + 8][c]) = __floats2half2_rn(d[nt][2], d[nt][3]);
    }
    __syncwarp();
    #pragma unroll
    for (int rr = 0; rr < 16; rr++) {
        int R = blockIdx.x * 64 + warp * 16 + rr;
        if (R < NN) {
            uint32 v = reinterpret_cast<const uint32*>(&outs[warp][rr][0])[lane];
            reinterpret_cast<uint32*>(g_h0h + (size_t)R * 32)[lane] = v;
        }
    }
}

// ---------------- GCN aggregate (+optional fused edge-head GEMV) ----------------
// One warp per node; lane owns 2 features. fp32 accumulate, fp16 output.
template <bool FUSE_HEAD>
__global__ __launch_bounds__(256) void k_agg(const float* __restrict__ bias,
                                             const float* __restrict__ Wl,
                                             const float* __restrict__ bl) {
    __shared__ float Wls[16 * 68];
    __shared__ float hs[8][64];
    __shared__ float blc[8];
    if (FUSE_HEAD) {
        for (int i = threadIdx.x; i < 16 * 64; i += 256) {
            int o = i & 15, k = i >> 4;
            int sel = o >> 3, oo = o & 7;
            Wls[o * 68 + k] = Wl[(sel * 64 + k) * 8 + oo];
        }
        if (threadIdx.x < 8) blc[threadIdx.x] = bl[threadIdx.x];
        __syncthreads();
    }

    int gw = (blockIdx.x * 256 + threadIdx.x) >> 5;   // grid exact: 12500 blocks
    int lane = threadIdx.x & 31;
    int w = threadIdx.x >> 5;
    float di = g_dinv[gw];
    int beg = g_rowptr[gw], end = g_rowptr[gw + 1];

    const __half2* hin = g_h0h;
    float2 hself = __half22float2(hin[(size_t)gw * 32 + lane]);
    float sw = di * di;
    float ax = sw * hself.x, ay = sw * hself.y;

    int e = beg;
    for (; e + 4 <= end; e += 4) {
        int2 p0 = __ldg(&g_srcw[e]);
        int2 p1 = __ldg(&g_srcw[e + 1]);
        int2 p2 = __ldg(&g_srcw[e + 2]);
        int2 p3 = __ldg(&g_srcw[e + 3]);
        float w0 = di * __int_as_float(p0.y);
        float w1 = di * __int_as_float(p1.y);
        float w2 = di * __int_as_float(p2.y);
        float w3 = di * __int_as_float(p3.y);
        float2 v0 = __half22float2(__ldg(&hin[(size_t)p0.x * 32 + lane]));
        float2 v1 = __half22float2(__ldg(&hin[(size_t)p1.x * 32 + lane]));
        float2 v2 = __half22float2(__ldg(&hin[(size_t)p2.x * 32 + lane]));
        float2 v3 = __half22float2(__ldg(&hin[(size_t)p3.x * 32 + lane]));
        ax += w0 * v0.x + w1 * v1.x + w2 * v2.x + w3 * v3.x;
        ay += w0 * v0.y + w1 * v1.y + w2 * v2.y + w3 * v3.y;
    }
    for (; e < end; e++) {
        int2 pp = __ldg(&g_srcw[e]);
        float wv = di * __int_as_float(pp.y);
        float2 v = __half22float2(__ldg(&hin[(size_t)pp.x * 32 + lane]));
        ax += wv * v.x;
        ay += wv * v.y;
    }
    float2 b = reinterpret_cast<const float2*>(bias)[lane];
    float rx = fmaxf(ax + b.x, 0.f);
    float ry = fmaxf(ay + b.y, 0.f);

    if (!FUSE_HEAD) {
        g_h1h[(size_t)gw * 32 + lane] = __floats2half2_rn(rx, ry);
    } else {
        hs[w][2 * lane + 0] = rx;
        hs[w][2 * lane + 1] = ry;
        __syncwarp();
        if (lane < 16) {
            float acc = (lane < 8) ? blc[lane] : 0.f;
            const float4* h4 = reinterpret_cast<const float4*>(hs[w]);
            const float4* w4 = reinterpret_cast<const float4*>(Wls + lane * 68);
            #pragma unroll
            for (int k4 = 0; k4 < 16; k4++) {
                float4 hv = h4[k4];
                float4 wv = w4[k4];
                acc += hv.x * wv.x + hv.y * wv.y + hv.z * wv.z + hv.w * wv.w;
            }
            g_y[(size_t)gw * 16 + lane] = acc;
        }
        __syncwarp();
    }
}

// ---------------- edge phase: out[e] = y[row][0:8] + y[col][8:16] ----------------
__global__ void k_edge(const int* __restrict__ row, const int* __restrict__ col,
                       float* __restrict__ out) {
    int idx = blockIdx.x * 256 + threadIdx.x;
    if (idx >= NE * 2) return;
    int e = idx >> 1, c = idx & 1;
    int r = row[e], cl = col[e];
    const float4* y4 = reinterpret_cast<const float4*>(g_y);
    float4 a = y4[(size_t)r * 4 + c];
    float4 b = y4[(size_t)cl * 4 + 2 + c];
    float4 o;
    o.x = a.x + b.x; o.y = a.y + b.y; o.z = a.z + b.z; o.w = a.w + b.w;
    reinterpret_cast<float4*>(out)[idx] = o;
}

// ---------------- launch ----------------
extern "C" void kernel_launch(void* const* d_in, const int* in_sizes, int n_in,
                              void* d_out, int out_size) {
    const float* x  = (const float*)d_in[0];
    const int*   ei = (const int*)  d_in[1];
    const float* W1 = (const float*)d_in[2];
    const float* b1 = (const float*)d_in[3];
    const float* W2 = (const float*)d_in[4];
    const float* b2 = (const float*)d_in[5];
    const float* Wl = (const float*)d_in[6];
    const float* bl = (const float*)d_in[7];
    float* out = (float*)d_out;

    const int* row = ei;        // edge_index[0]
    const int* col = ei + NE;   // edge_index[1]

    const int GEMM_G = (NN + 63) / 64;   // 1563 blocks (64 rows each)

    // fused CSR build
    k_csr<<<CSR_B, CSR_T>>>(row, col);

    // conv1: h0h = fp16(x@W1) ; h1h = fp16(relu(agg(h0h)+b1))
    k_gemm_mma<FIN, false><<<GEMM_G, 128>>>(x, W1);
    k_agg<false><<<(NN * 32) / 256, 256>>>(b1, Wl, bl);

    // conv2 + fused edge head (A = g_h1h selected inside device code)
    k_gemm_mma<HID, true><<<GEMM_G, 128>>>(nullptr, W2);
    k_agg<true><<<(NN * 32) / 256, 256>>>(b2, Wl, bl);

    // per-edge sum
    k_edge<<<(NE * 2 + 255) / 256, 256>>>(row, col, out);
}